// round 1
// baseline (speedup 1.0000x reference)
#include <cuda_runtime.h>

// Problem constants
#define Bn   2048
#define F0n  39
#define Dn   16
#define H1n  128
#define H2n  128
#define P1n  (F0n * F0n)   // 1521
#define P2n  (F0n * H1n)   // 4992
#define NCOL (Bn * Dn)     // 32768
#define BCOL 128           // columns (b,d) per block
#define HOUT (H1n + H2n)   // 256

#define XS_STRIDE  128
#define H1S_STRIDE 132     // padded to reduce bank conflicts in reductions

// Transposed weights: Wt[p][h] (allocation-free scratch)
__device__ float g_W0t[P1n * 128];
__device__ float g_W1t[P2n * 128];

typedef unsigned long long u64;

__device__ __forceinline__ u64 pack2(float lo, float hi) {
    u64 r; asm("mov.b64 %0, {%1, %2};" : "=l"(r) : "f"(lo), "f"(hi)); return r;
}
__device__ __forceinline__ void fma2(u64 &d, u64 a, u64 b) {
    asm("fma.rn.f32x2 %0, %1, %2, %0;" : "+l"(d) : "l"(a), "l"(b));
}
__device__ __forceinline__ u64 mul2(u64 a, u64 b) {
    u64 r; asm("mul.rn.f32x2 %0, %1, %2;" : "=l"(r) : "l"(a), "l"(b)); return r;
}
__device__ __forceinline__ float2 unpack2(u64 v) {
    float lo, hi; asm("mov.b64 {%0, %1}, %2;" : "=f"(lo), "=f"(hi) : "l"(v));
    float2 r; r.x = lo; r.y = hi; return r;
}

// W is [128, P] row-major; write Wt[p*128 + h]
__global__ void transpose_w0(const float* __restrict__ W) {
    int idx = blockIdx.x * blockDim.x + threadIdx.x;
    if (idx < 128 * P1n) {
        int h = idx / P1n; int p = idx - h * P1n;
        g_W0t[p * 128 + h] = W[idx];
    }
}
__global__ void transpose_w1(const float* __restrict__ W) {
    int idx = blockIdx.x * blockDim.x + threadIdx.x;
    if (idx < 128 * P2n) {
        int h = idx / P2n; int p = idx - h * P2n;
        g_W1t[p * 128 + h] = W[idx];
    }
}

__global__ __launch_bounds__(256, 2)
void cin_main(const float* __restrict__ x, float* __restrict__ out) {
    extern __shared__ float smem[];
    float* xs  = smem;                          // [F0n][XS_STRIDE]
    float* h1s = xs + F0n * XS_STRIDE;          // [128][H1S_STRIDE]
    float* wt  = h1s + H1n * H1S_STRIDE;        // [16][128]

    const int tid = threadIdx.x;
    const int tx = tid & 15;        // column group: cols tx*8 .. tx*8+7
    const int ty = tid >> 4;        // row group:    h = ty*8 .. ty*8+7
    const int cbase = tx * 8;
    const int b0 = blockIdx.x * (BCOL / Dn);   // 8 batches per block

    // ---- load x tile: xs[f][c], c = (b_local, d) ----
    for (int i = tid; i < F0n * BCOL; i += 256) {
        int f = i >> 7; int c = i & 127;
        int b = b0 + (c >> 4); int d = c & 15;
        xs[f * XS_STRIDE + c] = x[(b * F0n + f) * Dn + d];
    }
    __syncthreads();

    u64 acc[8][4];

    // ================= Layer 1: K = 1521, z = x[f]*x[q] =================
    #pragma unroll
    for (int i = 0; i < 8; i++)
        #pragma unroll
        for (int j = 0; j < 4; j++) acc[i][j] = 0ull;

    int f = 0, q = 0;
    for (int pc = 0; pc < P1n; pc += 16) {
        for (int i = tid; i < 16 * 128; i += 256) {
            int r = i >> 7, h = i & 127; int p = pc + r;
            wt[i] = (p < P1n) ? g_W0t[p * 128 + h] : 0.f;
        }
        __syncthreads();
        int rmax = min(16, P1n - pc);
        for (int r = 0; r < rmax; r++) {
            const u64* xf = (const u64*)&xs[f * XS_STRIDE + cbase];
            const u64* xq = (const u64*)&xs[q * XS_STRIDE + cbase];
            u64 z[4];
            #pragma unroll
            for (int j = 0; j < 4; j++) z[j] = mul2(xf[j], xq[j]);
            const float* ar = &wt[r * 128 + ty * 8];
            float4 a0 = *(const float4*)ar;
            float4 a1 = *(const float4*)(ar + 4);
            float av[8] = {a0.x, a0.y, a0.z, a0.w, a1.x, a1.y, a1.z, a1.w};
            #pragma unroll
            for (int i = 0; i < 8; i++) {
                u64 aa = pack2(av[i], av[i]);
                #pragma unroll
                for (int j = 0; j < 4; j++) fma2(acc[i][j], aa, z[j]);
            }
            if (++q == F0n) { q = 0; ++f; }
        }
        __syncthreads();
    }

    // stash h1 into smem (needed as the q-operand of layer 2)
    #pragma unroll
    for (int i = 0; i < 8; i++) {
        int h = ty * 8 + i;
        #pragma unroll
        for (int j = 0; j < 4; j++) {
            float2 v = unpack2(acc[i][j]);
            *(float2*)&h1s[h * H1S_STRIDE + cbase + 2 * j] = v;
        }
    }
    __syncthreads();

    // layer-1 output: out[b, h] = sum_d h1[h, (b,d)]
    for (int o = tid; o < H1n * 8; o += 256) {
        int h = o & 127; int bl = o >> 7;
        float s = 0.f;
        #pragma unroll
        for (int d = 0; d < 16; d++) s += h1s[h * H1S_STRIDE + bl * 16 + d];
        out[(b0 + bl) * HOUT + h] = s;
    }

    // ================= Layer 2: K = 4992, z = x[f]*h1[q] =================
    #pragma unroll
    for (int i = 0; i < 8; i++)
        #pragma unroll
        for (int j = 0; j < 4; j++) acc[i][j] = 0ull;

    for (int pc = 0; pc < P2n; pc += 16) {
        for (int i = tid; i < 16 * 128; i += 256) {
            int r = i >> 7, h = i & 127;
            wt[i] = g_W1t[(pc + r) * 128 + h];   // P2n % 16 == 0
        }
        __syncthreads();
        #pragma unroll 4
        for (int r = 0; r < 16; r++) {
            int p = pc + r;
            int ff = p >> 7, qq = p & 127;
            const u64* xf = (const u64*)&xs[ff * XS_STRIDE + cbase];
            const u64* hq = (const u64*)&h1s[qq * H1S_STRIDE + cbase];
            u64 z[4];
            #pragma unroll
            for (int j = 0; j < 4; j++) z[j] = mul2(xf[j], hq[j]);
            const float* ar = &wt[r * 128 + ty * 8];
            float4 a0 = *(const float4*)ar;
            float4 a1 = *(const float4*)(ar + 4);
            float av[8] = {a0.x, a0.y, a0.z, a0.w, a1.x, a1.y, a1.z, a1.w};
            #pragma unroll
            for (int i = 0; i < 8; i++) {
                u64 aa = pack2(av[i], av[i]);
                #pragma unroll
                for (int j = 0; j < 4; j++) fma2(acc[i][j], aa, z[j]);
            }
        }
        __syncthreads();
    }

    // layer-2 output: each thread reduces its 8 cols (8 d's of one b),
    // then combines with the partner lane (lane^1) holding the other 8 d's.
    {
        float tot[8];
        #pragma unroll
        for (int i = 0; i < 8; i++) {
            float s = 0.f;
            #pragma unroll
            for (int j = 0; j < 4; j++) {
                float2 v = unpack2(acc[i][j]);
                s += v.x + v.y;
            }
            s += __shfl_xor_sync(0xffffffffu, s, 1);
            tot[i] = s;
        }
        if ((tx & 1) == 0) {
            int bl = tx >> 1;
            float* dst = &out[(b0 + bl) * HOUT + H1n + ty * 8];
            float4 o0 = make_float4(tot[0], tot[1], tot[2], tot[3]);
            float4 o1 = make_float4(tot[4], tot[5], tot[6], tot[7]);
            *(float4*)dst = o0;
            *(float4*)(dst + 4) = o1;
        }
    }
}

#define SMEM_BYTES ((F0n * XS_STRIDE + H1n * H1S_STRIDE + 16 * 128) * (int)sizeof(float))

extern "C" void kernel_launch(void* const* d_in, const int* in_sizes, int n_in,
                              void* d_out, int out_size) {
    const float* xin = (const float*)d_in[0];
    const float* W0  = (const float*)d_in[1];
    const float* W1  = (const float*)d_in[2];
    float* out = (float*)d_out;

    transpose_w0<<<(128 * P1n + 255) / 256, 256>>>(W0);
    transpose_w1<<<(128 * P2n + 255) / 256, 256>>>(W1);

    cudaFuncSetAttribute(cin_main, cudaFuncAttributeMaxDynamicSharedMemorySize, SMEM_BYTES);
    cin_main<<<NCOL / BCOL, 256, SMEM_BYTES>>>(xin, out);
}

// round 3
// speedup vs baseline: 2.9903x; 2.9903x over previous
#include <cuda_runtime.h>
#include <cuda_bf16.h>
#include <cstdint>

#define K1    1521
#define K1P   1536
#define K2    4992
#define NC1   24            // 1536/64
#define NC2   78            // 4992/64
#define NCT   (NC1 + NC2)   // 102
#define F0n   39
#define Dn    16
#define HOUT  256

// ---- SMEM layout (bytes) ----
// buffer b (b=0,1) at b*65536: zhi[16384] zlo[16384] whi[16384] wlo[16384]
//   z tile: 128 n-rows x 64 k (128 B/row), XOR-swizzled
//   w tile: 128 h-rows x 64 k (128 B/row), XOR-swizzled
#define BUF_SZ    65536
#define XS_OFF    131072                  // float xs[128][40]
#define H1S_OFF   151552                  // float h1s[128][130]
#define SMEM_TOTAL 218112

// Pre-split weights, [chunk][h(128)][kl(64)] bf16, zero-padded past K1.
__device__ __nv_bfloat16 g_Whi[NCT * 8192];
__device__ __nv_bfloat16 g_Wlo[NCT * 8192];

__device__ __forceinline__ uint32_t smem_u32(const void* p) {
    uint32_t a;
    asm("{ .reg .u64 t; cvta.to.shared.u64 t, %1; cvt.u32.u64 %0, t; }" : "=r"(a) : "l"(p));
    return a;
}

#define CP16(dst, src) \
    asm volatile("cp.async.cg.shared.global [%0], [%1], 16;" :: "r"(dst), "l"(src))
#define CP_COMMIT() asm volatile("cp.async.commit_group;" ::: "memory")
#define CP_WAIT0()  asm volatile("cp.async.wait_group 0;" ::: "memory")

#define LDSM_X4(r0, r1, r2, r3, addr) \
    asm volatile("ldmatrix.sync.aligned.m8n8.x4.shared.b16 {%0,%1,%2,%3}, [%4];" \
                 : "=r"(r0), "=r"(r1), "=r"(r2), "=r"(r3) : "r"(addr))

#define MMA16816(d, a, b0_, b1_) \
    asm volatile("mma.sync.aligned.m16n8k16.row.col.f32.bf16.bf16.f32 " \
                 "{%0,%1,%2,%3}, {%4,%5,%6,%7}, {%8,%9}, {%0,%1,%2,%3};" \
                 : "+f"((d)[0]), "+f"((d)[1]), "+f"((d)[2]), "+f"((d)[3]) \
                 : "r"((a)[0]), "r"((a)[1]), "r"((a)[2]), "r"((a)[3]), \
                   "r"(b0_), "r"(b1_))

// ---------------- weight prep: split hi/lo bf16 ----------------
__global__ void prep_w(const float* __restrict__ W0, const float* __restrict__ W1) {
    int idx = blockIdx.x * 256 + threadIdx.x;
    if (idx >= NCT * 8192) return;
    int chunk = idx >> 13;
    int h = (idx >> 6) & 127;
    int kl = idx & 63;
    float w = 0.f;
    if (chunk < NC1) {
        int k = chunk * 64 + kl;
        if (k < K1) w = W0[h * K1 + k];
    } else {
        int k = (chunk - NC1) * 64 + kl;
        w = W1[h * K2 + k];
    }
    __nv_bfloat16 hi = __float2bfloat16(w);
    __nv_bfloat16 lo = __float2bfloat16(w - __bfloat162float(hi));
    g_Whi[idx] = hi;
    g_Wlo[idx] = lo;
}

// ---------------- device helpers ----------------
__device__ __forceinline__ void stage_w(uint32_t sb, int bb, int chunk, int tid) {
    const uint32_t wbase = sb + bb * BUF_SZ + 32768;
    #pragma unroll
    for (int t = 0; t < 8; t++) {
        int i = tid + t * 256;            // 0..2047
        int tile = i >> 10;               // 0=hi, 1=lo
        int h = (i >> 3) & 127;
        int seg = i & 7;
        const __nv_bfloat16* src =
            (tile ? g_Wlo : g_Whi) + chunk * 8192 + h * 64 + seg * 8;
        uint32_t dst = wbase + tile * 16384 + h * 128 + ((seg * 16) ^ ((h & 7) << 4));
        CP16(dst, src);
    }
}

__device__ __forceinline__ void build_z(char* smem, int bb, int layer, int c, int tid) {
    const float* xs  = (const float*)(smem + XS_OFF);
    const float* h1s = (const float*)(smem + H1S_OFF);
    char* zhi = smem + bb * BUF_SZ;
    char* zlo = zhi + 16384;
    const int kl = tid & 63;
    const int n0 = (tid >> 6) * 32;
    const int k = c * 64 + kl;
    int f = 0, q = 0;
    bool valid = true;
    if (layer == 0) {
        if (k < K1) { f = k / 39; q = k - f * 39; } else valid = false;
    } else { f = k >> 7; q = k & 127; }
    const uint32_t cb = (uint32_t)(kl * 2);
    #pragma unroll 8
    for (int nn = 0; nn < 32; nn++) {
        const int n = n0 + nn;
        float zv = 0.f;
        if (valid) {
            float a = xs[n * 40 + f];
            float b = layer ? h1s[n * 130 + q] : xs[n * 40 + q];
            zv = a * b;
        }
        __nv_bfloat16 hi = __float2bfloat16(zv);
        __nv_bfloat16 lo = __float2bfloat16(zv - __bfloat162float(hi));
        uint32_t off = (uint32_t)(n * 128) + (cb ^ ((uint32_t)(n & 7) << 4));
        *(__nv_bfloat16*)(zhi + off) = hi;
        *(__nv_bfloat16*)(zlo + off) = lo;
    }
}

__device__ __forceinline__ void mma_chunk(uint32_t sb, int bb, float acc[4][4][4],
                                          int m0, int h0, int lane) {
    const uint32_t zb = sb + bb * BUF_SZ;
    const uint32_t wb = zb + 32768;
    #pragma unroll
    for (int ks = 0; ks < 4; ks++) {
        const int kb = ks * 16;
        uint32_t a_hi[4][4], a_lo[4][4];
        const uint32_t acolb = (uint32_t)((kb + (lane >> 4) * 8) * 2);
        #pragma unroll
        for (int mt = 0; mt < 4; mt++) {
            const int n = m0 + mt * 16 + (lane & 15);
            const uint32_t ad = zb + n * 128 + (acolb ^ ((uint32_t)(n & 7) << 4));
            LDSM_X4(a_hi[mt][0], a_hi[mt][1], a_hi[mt][2], a_hi[mt][3], ad);
            LDSM_X4(a_lo[mt][0], a_lo[mt][1], a_lo[mt][2], a_lo[mt][3], ad + 16384);
        }
        uint32_t b_hi[8], b_lo[8];
        const uint32_t bcolb = (uint32_t)((kb + ((lane >> 3) & 1) * 8) * 2);
        #pragma unroll
        for (int pr = 0; pr < 2; pr++) {
            const int h = h0 + pr * 16 + (lane >> 4) * 8 + (lane & 7);
            const uint32_t bd = wb + h * 128 + (bcolb ^ ((uint32_t)(h & 7) << 4));
            LDSM_X4(b_hi[pr * 4 + 0], b_hi[pr * 4 + 1], b_hi[pr * 4 + 2], b_hi[pr * 4 + 3], bd);
            LDSM_X4(b_lo[pr * 4 + 0], b_lo[pr * 4 + 1], b_lo[pr * 4 + 2], b_lo[pr * 4 + 3], bd + 16384);
        }
        #pragma unroll
        for (int mt = 0; mt < 4; mt++)
            #pragma unroll
            for (int ht = 0; ht < 4; ht++) {
                MMA16816(acc[mt][ht], a_hi[mt], b_hi[ht * 2], b_hi[ht * 2 + 1]);
                MMA16816(acc[mt][ht], a_hi[mt], b_lo[ht * 2], b_lo[ht * 2 + 1]);
                MMA16816(acc[mt][ht], a_lo[mt], b_hi[ht * 2], b_hi[ht * 2 + 1]);
            }
    }
}

// ---------------- main kernel ----------------
__global__ __launch_bounds__(256, 1)
void cin_main(const float* __restrict__ x, float* __restrict__ out) {
    extern __shared__ __align__(1024) char smem[];
    const uint32_t sb = smem_u32(smem);
    float* xs  = (float*)(smem + XS_OFF);
    float* h1s = (float*)(smem + H1S_OFF);

    const int tid = threadIdx.x;
    const int lane = tid & 31;
    const int warp = tid >> 5;
    const int m0 = (warp & 1) * 64;       // n-rows
    const int h0 = (warp >> 1) * 32;      // h-cols
    const int b0 = blockIdx.x * 8;

    // load x tile transposed: xs[n][f], n = (b_local<<4)|d
    for (int i = tid; i < F0n * 128; i += 256) {
        int f = i >> 7, c = i & 127;
        int b = b0 + (c >> 4), d = c & 15;
        xs[c * 40 + f] = x[(b * F0n + f) * Dn + d];
    }
    __syncthreads();

    float acc[4][4][4];

    #pragma unroll 1
    for (int layer = 0; layer < 2; layer++) {
        const int nc = layer ? NC2 : NC1;
        const int cbase = layer ? NC1 : 0;

        #pragma unroll
        for (int mt = 0; mt < 4; mt++)
            #pragma unroll
            for (int ht = 0; ht < 4; ht++)
                #pragma unroll
                for (int j = 0; j < 4; j++) acc[mt][ht][j] = 0.f;

        // prologue: stage + build chunk 0
        stage_w(sb, 0, cbase, tid);
        CP_COMMIT();
        build_z(smem, 0, layer, 0, tid);
        CP_WAIT0();
        __syncthreads();

        #pragma unroll 1
        for (int c = 0; c < nc; c++) {
            const int bb = c & 1;
            const int nb = bb ^ 1;
            if (c + 1 < nc) { stage_w(sb, nb, cbase + c + 1, tid); CP_COMMIT(); }
            mma_chunk(sb, bb, acc, m0, h0, lane);
            if (c + 1 < nc) build_z(smem, nb, layer, c + 1, tid);
            CP_WAIT0();
            __syncthreads();
        }

        // store acc -> h1s[n][h] (fp32)
        {
            const int r = lane >> 2;
            const int cc = (lane & 3) * 2;
            #pragma unroll
            for (int mt = 0; mt < 4; mt++)
                #pragma unroll
                for (int ht = 0; ht < 4; ht++) {
                    const int n = m0 + mt * 16 + r;
                    const int h = h0 + ht * 8 + cc;
                    *(float2*)&h1s[n * 130 + h] =
                        make_float2(acc[mt][ht][0], acc[mt][ht][1]);
                    *(float2*)&h1s[(n + 8) * 130 + h] =
                        make_float2(acc[mt][ht][2], acc[mt][ht][3]);
                }
        }
        __syncthreads();

        // out[b][h] = sum_d h1s[(bl*16+d)][h]
        const int obase = layer ? 128 : 0;
        #pragma unroll
        for (int rr = 0; rr < 4; rr++) {
            const int idx = rr * 256 + tid;
            const int bl = idx >> 7, h = idx & 127;
            float s = 0.f;
            #pragma unroll
            for (int d = 0; d < 16; d++) s += h1s[(bl * 16 + d) * 130 + h];
            out[(b0 + bl) * HOUT + obase + h] = s;
        }
        __syncthreads();
    }
}

extern "C" void kernel_launch(void* const* d_in, const int* in_sizes, int n_in,
                              void* d_out, int out_size) {
    const float* xin = (const float*)d_in[0];
    const float* W0  = (const float*)d_in[1];
    const float* W1  = (const float*)d_in[2];
    float* out = (float*)d_out;

    prep_w<<<(NCT * 8192 + 255) / 256, 256>>>(W0, W1);

    cudaFuncSetAttribute(cin_main, cudaFuncAttributeMaxDynamicSharedMemorySize, SMEM_TOTAL);
    cin_main<<<256, 256, SMEM_TOTAL>>>(xin, out);
}

// round 4
// speedup vs baseline: 3.6179x; 1.2098x over previous
#include <cuda_runtime.h>
#include <cuda_bf16.h>
#include <cstdint>

#define K1    1521
#define K1P   1536
#define K2    4992
#define NC1   24            // 1536/64
#define NC2   78            // 4992/64
#define NCT   (NC1 + NC2)   // 102
#define F0n   39
#define Dn    16
#define HOUT  256

// ---- SMEM layout (bytes) ----
// buffer b (b=0,1) at b*65536: zhi[16384] zlo[16384] whi[16384] wlo[16384]
//   z tile: 128 n-rows x 64 k (128 B/row), XOR-swizzled
//   w tile: 128 h-rows x 64 k (128 B/row), XOR-swizzled
#define BUF_SZ    65536
#define XS_OFF    131072                  // float xs[128][40]
#define H1S_OFF   151552                  // float h1s[128][130]
#define SMEM_TOTAL 218112

// Pre-split weights, [chunk][h(128)][kl(64)] bf16, zero-padded past K1.
__device__ __nv_bfloat16 g_Whi[NCT * 8192];
__device__ __nv_bfloat16 g_Wlo[NCT * 8192];

__device__ __forceinline__ uint32_t smem_u32(const void* p) {
    uint32_t a;
    asm("{ .reg .u64 t; cvta.to.shared.u64 t, %1; cvt.u32.u64 %0, t; }" : "=r"(a) : "l"(p));
    return a;
}

#define CP16(dst, src) \
    asm volatile("cp.async.cg.shared.global [%0], [%1], 16;" :: "r"(dst), "l"(src))
#define CP_COMMIT() asm volatile("cp.async.commit_group;" ::: "memory")
#define CP_WAIT0()  asm volatile("cp.async.wait_group 0;" ::: "memory")

#define LDSM_X4(r0, r1, r2, r3, addr) \
    asm volatile("ldmatrix.sync.aligned.m8n8.x4.shared.b16 {%0,%1,%2,%3}, [%4];" \
                 : "=r"(r0), "=r"(r1), "=r"(r2), "=r"(r3) : "r"(addr))

#define MMA16816(d, a, b0_, b1_) \
    asm volatile("mma.sync.aligned.m16n8k16.row.col.f32.bf16.bf16.f32 " \
                 "{%0,%1,%2,%3}, {%4,%5,%6,%7}, {%8,%9}, {%0,%1,%2,%3};" \
                 : "+f"((d)[0]), "+f"((d)[1]), "+f"((d)[2]), "+f"((d)[3]) \
                 : "r"((a)[0]), "r"((a)[1]), "r"((a)[2]), "r"((a)[3]), \
                   "r"(b0_), "r"(b1_))

// ---------------- weight prep: split hi/lo bf16 ----------------
__global__ void prep_w(const float* __restrict__ W0, const float* __restrict__ W1) {
    int idx = blockIdx.x * 256 + threadIdx.x;
    if (idx >= NCT * 8192) return;
    int chunk = idx >> 13;
    int h = (idx >> 6) & 127;
    int kl = idx & 63;
    float w = 0.f;
    if (chunk < NC1) {
        int k = chunk * 64 + kl;
        if (k < K1) w = W0[h * K1 + k];
    } else {
        int k = (chunk - NC1) * 64 + kl;
        w = W1[h * K2 + k];
    }
    __nv_bfloat16 hi = __float2bfloat16(w);
    __nv_bfloat16 lo = __float2bfloat16(w - __bfloat162float(hi));
    g_Whi[idx] = hi;
    g_Wlo[idx] = lo;
}

// ---------------- device helpers ----------------
__device__ __forceinline__ void stage_w(uint32_t sb, int bb, int chunk, int tid) {
    const uint32_t wbase = sb + bb * BUF_SZ + 32768;
    #pragma unroll
    for (int t = 0; t < 4; t++) {
        int i = tid + t * 512;            // 0..2047
        int tile = i >> 10;               // 0=hi, 1=lo
        int h = (i >> 3) & 127;
        int seg = i & 7;
        const __nv_bfloat16* src =
            (tile ? g_Wlo : g_Whi) + chunk * 8192 + h * 64 + seg * 8;
        uint32_t dst = wbase + tile * 16384 + h * 128 + ((seg * 16) ^ ((h & 7) << 4));
        CP16(dst, src);
    }
}

__device__ __forceinline__ void build_z(char* smem, int bb, int layer, int c, int tid) {
    const float* xs  = (const float*)(smem + XS_OFF);
    const float* h1s = (const float*)(smem + H1S_OFF);
    char* zhi = smem + bb * BUF_SZ;
    char* zlo = zhi + 16384;
    const int kl = tid & 63;
    const int n0 = (tid >> 6) * 16;       // 8 groups of 16 rows
    const int k = c * 64 + kl;
    int f = 0, q = 0;
    bool valid = true;
    if (layer == 0) {
        if (k < K1) { f = k / 39; q = k - f * 39; } else valid = false;
    } else { f = k >> 7; q = k & 127; }
    const uint32_t cb = (uint32_t)(kl * 2);
    #pragma unroll 8
    for (int nn = 0; nn < 16; nn++) {
        const int n = n0 + nn;
        float zv = 0.f;
        if (valid) {
            float a = xs[n * 40 + f];
            float b = layer ? h1s[n * 130 + q] : xs[n * 40 + q];
            zv = a * b;
        }
        __nv_bfloat16 hi = __float2bfloat16(zv);
        __nv_bfloat16 lo = __float2bfloat16(zv - __bfloat162float(hi));
        uint32_t off = (uint32_t)(n * 128) + (cb ^ ((uint32_t)(n & 7) << 4));
        *(__nv_bfloat16*)(zhi + off) = hi;
        *(__nv_bfloat16*)(zlo + off) = lo;
    }
}

__device__ __forceinline__ void mma_chunk(uint32_t sb, int bb, float acc[2][4][4],
                                          int m0, int h0, int lane) {
    const uint32_t zb = sb + bb * BUF_SZ;
    const uint32_t wb = zb + 32768;
    #pragma unroll
    for (int ks = 0; ks < 4; ks++) {
        const int kb = ks * 16;
        uint32_t a_hi[2][4], a_lo[2][4];
        const uint32_t acolb = (uint32_t)((kb + (lane >> 4) * 8) * 2);
        #pragma unroll
        for (int mt = 0; mt < 2; mt++) {
            const int n = m0 + mt * 16 + (lane & 15);
            const uint32_t ad = zb + n * 128 + (acolb ^ ((uint32_t)(n & 7) << 4));
            LDSM_X4(a_hi[mt][0], a_hi[mt][1], a_hi[mt][2], a_hi[mt][3], ad);
            LDSM_X4(a_lo[mt][0], a_lo[mt][1], a_lo[mt][2], a_lo[mt][3], ad + 16384);
        }
        uint32_t b_hi[8], b_lo[8];
        const uint32_t bcolb = (uint32_t)((kb + ((lane >> 3) & 1) * 8) * 2);
        #pragma unroll
        for (int pr = 0; pr < 2; pr++) {
            const int h = h0 + pr * 16 + (lane >> 4) * 8 + (lane & 7);
            const uint32_t bd = wb + h * 128 + (bcolb ^ ((uint32_t)(h & 7) << 4));
            LDSM_X4(b_hi[pr * 4 + 0], b_hi[pr * 4 + 1], b_hi[pr * 4 + 2], b_hi[pr * 4 + 3], bd);
            LDSM_X4(b_lo[pr * 4 + 0], b_lo[pr * 4 + 1], b_lo[pr * 4 + 2], b_lo[pr * 4 + 3], bd + 16384);
        }
        #pragma unroll
        for (int mt = 0; mt < 2; mt++)
            #pragma unroll
            for (int ht = 0; ht < 4; ht++) {
                MMA16816(acc[mt][ht], a_hi[mt], b_hi[ht * 2], b_hi[ht * 2 + 1]);
                MMA16816(acc[mt][ht], a_hi[mt], b_lo[ht * 2], b_lo[ht * 2 + 1]);
                MMA16816(acc[mt][ht], a_lo[mt], b_hi[ht * 2], b_hi[ht * 2 + 1]);
            }
    }
}

// ---------------- main kernel ----------------
__global__ __launch_bounds__(512, 1)
void cin_main(const float* __restrict__ x, float* __restrict__ out) {
    extern __shared__ __align__(1024) char smem[];
    const uint32_t sb = smem_u32(smem);
    float* xs  = (float*)(smem + XS_OFF);
    float* h1s = (float*)(smem + H1S_OFF);

    const int tid = threadIdx.x;
    const int lane = tid & 31;
    const int warp = tid >> 5;
    const int m0 = (warp & 3) * 32;       // n-rows (4 groups of 32)
    const int h0 = (warp >> 2) * 32;      // h-cols (4 groups of 32)
    const int b0 = blockIdx.x * 8;

    // load x tile transposed: xs[n][f], n = (b_local<<4)|d
    for (int i = tid; i < F0n * 128; i += 512) {
        int f = i >> 7, c = i & 127;
        int b = b0 + (c >> 4), d = c & 15;
        xs[c * 40 + f] = x[(b * F0n + f) * Dn + d];
    }
    __syncthreads();

    float acc[2][4][4];

    #pragma unroll 1
    for (int layer = 0; layer < 2; layer++) {
        const int nc = layer ? NC2 : NC1;
        const int cbase = layer ? NC1 : 0;

        #pragma unroll
        for (int mt = 0; mt < 2; mt++)
            #pragma unroll
            for (int ht = 0; ht < 4; ht++)
                #pragma unroll
                for (int j = 0; j < 4; j++) acc[mt][ht][j] = 0.f;

        // prologue: stage + build chunk 0
        stage_w(sb, 0, cbase, tid);
        CP_COMMIT();
        build_z(smem, 0, layer, 0, tid);
        CP_WAIT0();
        __syncthreads();

        #pragma unroll 1
        for (int c = 0; c < nc; c++) {
            const int bb = c & 1;
            const int nb = bb ^ 1;
            if (c + 1 < nc) { stage_w(sb, nb, cbase + c + 1, tid); CP_COMMIT(); }
            mma_chunk(sb, bb, acc, m0, h0, lane);
            if (c + 1 < nc) build_z(smem, nb, layer, c + 1, tid);
            CP_WAIT0();
            __syncthreads();
        }

        // store acc -> h1s[n][h] (fp32)
        {
            const int r = lane >> 2;
            const int cc = (lane & 3) * 2;
            #pragma unroll
            for (int mt = 0; mt < 2; mt++)
                #pragma unroll
                for (int ht = 0; ht < 4; ht++) {
                    const int n = m0 + mt * 16 + r;
                    const int h = h0 + ht * 8 + cc;
                    *(float2*)&h1s[n * 130 + h] =
                        make_float2(acc[mt][ht][0], acc[mt][ht][1]);
                    *(float2*)&h1s[(n + 8) * 130 + h] =
                        make_float2(acc[mt][ht][2], acc[mt][ht][3]);
                }
        }
        __syncthreads();

        // out[b][h] = sum_d h1s[(bl*16+d)][h]
        const int obase = layer ? 128 : 0;
        #pragma unroll
        for (int rr = 0; rr < 2; rr++) {
            const int idx = rr * 512 + tid;
            const int bl = idx >> 7, h = idx & 127;
            float s = 0.f;
            #pragma unroll
            for (int d = 0; d < 16; d++) s += h1s[(bl * 16 + d) * 130 + h];
            out[(b0 + bl) * HOUT + obase + h] = s;
        }
        __syncthreads();
    }
}

extern "C" void kernel_launch(void* const* d_in, const int* in_sizes, int n_in,
                              void* d_out, int out_size) {
    const float* xin = (const float*)d_in[0];
    const float* W0  = (const float*)d_in[1];
    const float* W1  = (const float*)d_in[2];
    float* out = (float*)d_out;

    prep_w<<<(NCT * 8192 + 255) / 256, 256>>>(W0, W1);

    cudaFuncSetAttribute(cin_main, cudaFuncAttributeMaxDynamicSharedMemorySize, SMEM_TOTAL);
    cin_main<<<256, 512, SMEM_TOTAL>>>(xin, out);
}